// round 6
// baseline (speedup 1.0000x reference)
#include <cuda_runtime.h>

// Loss_46883863003176: out = sum((pred - tgt)^2) / S / B
// pred, tgt: (4096, 2047, 2) float32, contiguous. Pure HBM-bound reduction.
//
// Fused single kernel, last-block-done finish. Grid shaped to kill the
// multi-CTA completion spread: 2 CTAs/SM x 1024 threads (oe=2, MLP_p1=8 ->
// oe*MLP_p1 = 16 = L1tex queue soft threshold -> spread ~ floor 1.10).

#define BLOCK_THREADS 1024
#define NUM_BLOCKS    (148 * 2)   // 296 CTAs, 2 per SM, 64 warps/SM

__device__ float        g_partials[NUM_BLOCKS];
__device__ unsigned int g_arrival = 0;   // wraps to 0 every NUM_BLOCKS arrivals

__global__ void __launch_bounds__(BLOCK_THREADS, 2)
mse_fused_kernel(const float4* __restrict__ pred,
                 const float4* __restrict__ tgt,
                 float* __restrict__ out,
                 int n_vec4,          // number of float4 elements
                 float inv_norm)      // 1 / (S * B)
{
    const int tid     = threadIdx.x;
    const int gthread = blockIdx.x * BLOCK_THREADS + tid;
    const int stride  = gridDim.x * BLOCK_THREADS;   // 303,104

    float acc = 0.0f;

    // Unroll-by-4 grid-stride: 8 independent LDG.128 in flight per iteration.
    int i = gthread;
    for (; i + 3 * stride < n_vec4; i += 4 * stride) {
        float4 p0 = __ldg(&pred[i]);
        float4 p1 = __ldg(&pred[i + stride]);
        float4 p2 = __ldg(&pred[i + 2 * stride]);
        float4 p3 = __ldg(&pred[i + 3 * stride]);
        float4 t0 = __ldg(&tgt[i]);
        float4 t1 = __ldg(&tgt[i + stride]);
        float4 t2 = __ldg(&tgt[i + 2 * stride]);
        float4 t3 = __ldg(&tgt[i + 3 * stride]);

        float d;
        d = p0.x - t0.x; acc = fmaf(d, d, acc);
        d = p0.y - t0.y; acc = fmaf(d, d, acc);
        d = p0.z - t0.z; acc = fmaf(d, d, acc);
        d = p0.w - t0.w; acc = fmaf(d, d, acc);
        d = p1.x - t1.x; acc = fmaf(d, d, acc);
        d = p1.y - t1.y; acc = fmaf(d, d, acc);
        d = p1.z - t1.z; acc = fmaf(d, d, acc);
        d = p1.w - t1.w; acc = fmaf(d, d, acc);
        d = p2.x - t2.x; acc = fmaf(d, d, acc);
        d = p2.y - t2.y; acc = fmaf(d, d, acc);
        d = p2.z - t2.z; acc = fmaf(d, d, acc);
        d = p2.w - t2.w; acc = fmaf(d, d, acc);
        d = p3.x - t3.x; acc = fmaf(d, d, acc);
        d = p3.y - t3.y; acc = fmaf(d, d, acc);
        d = p3.z - t3.z; acc = fmaf(d, d, acc);
        d = p3.w - t3.w; acc = fmaf(d, d, acc);
    }
    // Tail: up to 3 vectors per thread
    for (; i < n_vec4; i += stride) {
        float4 p = __ldg(&pred[i]);
        float4 t = __ldg(&tgt[i]);
        float d;
        d = p.x - t.x; acc = fmaf(d, d, acc);
        d = p.y - t.y; acc = fmaf(d, d, acc);
        d = p.z - t.z; acc = fmaf(d, d, acc);
        d = p.w - t.w; acc = fmaf(d, d, acc);
    }

    // Warp reduce
    #pragma unroll
    for (int off = 16; off > 0; off >>= 1)
        acc += __shfl_xor_sync(0xFFFFFFFFu, acc, off);

    // Block reduce via shared
    __shared__ float warp_sums[BLOCK_THREADS / 32];   // 32
    __shared__ bool  is_last;
    const int lane = tid & 31;
    const int wid  = tid >> 5;
    if (lane == 0) warp_sums[wid] = acc;
    __syncthreads();

    if (wid == 0) {
        float v = warp_sums[lane];   // 32 warps -> all lanes valid
        #pragma unroll
        for (int off = 16; off > 0; off >>= 1)
            v += __shfl_xor_sync(0xFFFFFFFFu, v, off);
        if (lane == 0) {
            g_partials[blockIdx.x] = v;
            __threadfence();
            // atomicInc wraps to 0 at NUM_BLOCKS-1 -> self-resets every launch,
            // keeping graph replays deterministic.
            unsigned int prev = atomicInc(&g_arrival, NUM_BLOCKS - 1);
            is_last = (prev == NUM_BLOCKS - 1);
        }
    }
    __syncthreads();

    // Last block to arrive performs the final reduction (first warp suffices:
    // 296 partials, lane-strided).
    if (is_last && wid == 0) {
        float v = 0.0f;
        for (int b = lane; b < NUM_BLOCKS; b += 32)
            v += g_partials[b];

        #pragma unroll
        for (int off = 16; off > 0; off >>= 1)
            v += __shfl_xor_sync(0xFFFFFFFFu, v, off);

        if (lane == 0)
            out[0] = v * inv_norm;   // overwrite poisoned d_out
    }
}

extern "C" void kernel_launch(void* const* d_in, const int* in_sizes, int n_in,
                              void* d_out, int out_size)
{
    const float* pred = (const float*)d_in[0];
    const float* tgt  = (const float*)d_in[1];
    float* out = (float*)d_out;

    const long long total = (long long)in_sizes[0];   // B * S * 2 = 16,769,024
    const int n_vec4 = (int)(total / 4);              // divisible by 4
    // normalizer: S * B = total / 2
    const float inv_norm = 2.0f / (float)total;

    mse_fused_kernel<<<NUM_BLOCKS, BLOCK_THREADS>>>(
        (const float4*)pred, (const float4*)tgt, out, n_vec4, inv_norm);
}

// round 7
// speedup vs baseline: 1.1633x; 1.1633x over previous
#include <cuda_runtime.h>

// Loss_46883863003176: out = sum((pred - tgt)^2) / S / B
// pred, tgt: (4096, 2047, 2) float32, contiguous. Pure HBM-bound reduction.
//
// Single fused kernel. Each block atomically adds its PRE-SCALED partial into a
// device accumulator; the last-arriving block (wraparound counter, self-reset
// across graph replays) copies the total to d_out and resets the accumulator.
// No second launch, no partials-array reduce loop, no memset, no allocations.

#define BLOCK_THREADS 256
#define NUM_BLOCKS    (148 * 8)   // 1184 CTAs, 8/SM, 64 warps/SM (R3-proven shape)

__device__ float        g_accum   = 0.0f;  // running sum (reset by winner each launch)
__device__ unsigned int g_arrival = 0;     // wraps to 0 every NUM_BLOCKS arrivals

__global__ void __launch_bounds__(BLOCK_THREADS)
mse_fused_kernel(const float4* __restrict__ pred,
                 const float4* __restrict__ tgt,
                 float* __restrict__ out,
                 int n_vec4,          // number of float4 elements
                 float inv_norm)      // 1 / (S * B)
{
    const int tid     = threadIdx.x;
    const int gthread = blockIdx.x * BLOCK_THREADS + tid;
    const int stride  = gridDim.x * BLOCK_THREADS;

    float acc = 0.0f;

    // Unroll-by-2 grid-stride: 4 independent LDG.128 in flight per iteration.
    // __ldcs: streaming (evict-first) — data is touch-once.
    int i = gthread;
    for (; i + stride < n_vec4; i += 2 * stride) {
        float4 p0 = __ldcs(&pred[i]);
        float4 t0 = __ldcs(&tgt[i]);
        float4 p1 = __ldcs(&pred[i + stride]);
        float4 t1 = __ldcs(&tgt[i + stride]);

        float d;
        d = p0.x - t0.x; acc = fmaf(d, d, acc);
        d = p0.y - t0.y; acc = fmaf(d, d, acc);
        d = p0.z - t0.z; acc = fmaf(d, d, acc);
        d = p0.w - t0.w; acc = fmaf(d, d, acc);
        d = p1.x - t1.x; acc = fmaf(d, d, acc);
        d = p1.y - t1.y; acc = fmaf(d, d, acc);
        d = p1.z - t1.z; acc = fmaf(d, d, acc);
        d = p1.w - t1.w; acc = fmaf(d, d, acc);
    }
    // Tail (at most one vector per thread)
    if (i < n_vec4) {
        float4 p = __ldcs(&pred[i]);
        float4 t = __ldcs(&tgt[i]);
        float d;
        d = p.x - t.x; acc = fmaf(d, d, acc);
        d = p.y - t.y; acc = fmaf(d, d, acc);
        d = p.z - t.z; acc = fmaf(d, d, acc);
        d = p.w - t.w; acc = fmaf(d, d, acc);
    }

    // Warp reduce
    #pragma unroll
    for (int off = 16; off > 0; off >>= 1)
        acc += __shfl_xor_sync(0xFFFFFFFFu, acc, off);

    // Block reduce via shared
    __shared__ float warp_sums[BLOCK_THREADS / 32];
    __shared__ bool  is_last;
    const int lane = tid & 31;
    const int wid  = tid >> 5;
    if (lane == 0) warp_sums[wid] = acc;
    __syncthreads();

    if (tid == 0) {
        float v = 0.0f;
        #pragma unroll
        for (int w = 0; w < BLOCK_THREADS / 32; w++)
            v += warp_sums[w];

        // Pre-scale so the final value needs no further math.
        atomicAdd(&g_accum, v * inv_norm);
        __threadfence();   // order the add before the arrival increment
        // atomicInc wraps to 0 at NUM_BLOCKS-1 -> self-resets each launch,
        // keeping graph replays deterministic.
        unsigned int prev = atomicInc(&g_arrival, NUM_BLOCKS - 1);
        is_last = (prev == NUM_BLOCKS - 1);
    }
    __syncthreads();

    // Last block: publish result, reset accumulator for the next replay.
    if (is_last && tid == 0) {
        // All 1183 other blocks fenced their adds before arriving, and this
        // block observed all arrivals -> g_accum is complete.
        float total = atomicAdd(&g_accum, 0.0f);   // atomic read
        out[0] = total;                             // overwrite poisoned d_out
        __threadfence();
        atomicExch(&g_accum, 0.0f);                 // reset for next launch
    }
}

extern "C" void kernel_launch(void* const* d_in, const int* in_sizes, int n_in,
                              void* d_out, int out_size)
{
    const float* pred = (const float*)d_in[0];
    const float* tgt  = (const float*)d_in[1];
    float* out = (float*)d_out;

    const long long total = (long long)in_sizes[0];   // B * S * 2 = 16,769,024
    const int n_vec4 = (int)(total / 4);              // divisible by 4
    // normalizer: S * B = total / 2
    const float inv_norm = 2.0f / (float)total;

    mse_fused_kernel<<<NUM_BLOCKS, BLOCK_THREADS>>>(
        (const float4*)pred, (const float4*)tgt, out, n_vec4, inv_norm);
}